// round 1
// baseline (speedup 1.0000x reference)
#include <cuda_runtime.h>

#define Bb 32
#define Dd 2048
#define Tt 512
#define Kk 512
#define Nn (Bb*Tt)            // 16384
#define BDT (Bb*Dd*Tt)        // 33554432
#define OH1_OFF BDT           // z_q_x_onehot
#define BAR_OFF (BDT + Nn)    // z_q_x_bar
#define OH2_OFF (2*BDT + Nn)  // z_q_x_bar_onehot

// Scratch (device globals: allocation-free per harness rules)
__device__ float g_dots[(size_t)Nn * Kk];   // 32 MB score matrix
__device__ float g_S[Nn];
__device__ float g_C2[Kk];
__device__ int   g_idx[Nn];

// ---------------------------------------------------------------------------
// C2[k] = sum_d codebook[k,d]^2
// ---------------------------------------------------------------------------
__global__ void k_c2(const float* __restrict__ cb) {
    int k = blockIdx.x;
    const float4* row = (const float4*)(cb + (size_t)k * Dd);
    float s = 0.f;
    for (int i = threadIdx.x; i < Dd / 4; i += 256) {
        float4 v = row[i];
        s += v.x * v.x + v.y * v.y + v.z * v.z + v.w * v.w;
    }
    __shared__ float sm[256];
    sm[threadIdx.x] = s;
    __syncthreads();
    for (int o = 128; o; o >>= 1) {
        if (threadIdx.x < o) sm[threadIdx.x] += sm[threadIdx.x + o];
        __syncthreads();
    }
    if (threadIdx.x == 0) g_C2[k] = sm[0];
}

// ---------------------------------------------------------------------------
// S[n] = sum_d z[b,d,t]^2   (n = b*T + t; z is (B, D, T))
// ---------------------------------------------------------------------------
__global__ void k_S(const float* __restrict__ z) {
    int n = blockIdx.x * 256 + threadIdx.x;
    int b = n / Tt, t = n % Tt;
    const float* p = z + (size_t)b * Dd * Tt + t;
    float a0 = 0.f, a1 = 0.f, a2 = 0.f, a3 = 0.f;
#pragma unroll 4
    for (int d = 0; d < Dd; d += 4) {
        float v0 = p[(size_t)(d + 0) * Tt];
        float v1 = p[(size_t)(d + 1) * Tt];
        float v2 = p[(size_t)(d + 2) * Tt];
        float v3 = p[(size_t)(d + 3) * Tt];
        a0 += v0 * v0; a1 += v1 * v1; a2 += v2 * v2; a3 += v3 * v3;
    }
    g_S[n] = (a0 + a1) + (a2 + a3);
}

// ---------------------------------------------------------------------------
// GEMM: dots[n,k] = sum_d A[n,d] * cb[k,d]
//   A[n,d] lives at z[b*D*T + d*T + t]  (n = b*T + t)
// 128x128 block tile, BK=16, 8x8 micro-tile, 256 threads.
// ---------------------------------------------------------------------------
__global__ void __launch_bounds__(256, 1) k_gemm(const float* __restrict__ z,
                                                 const float* __restrict__ cb) {
    __shared__ float As[16][128];
    __shared__ float Bs[16][132];

    int k0 = blockIdx.x * 128;
    int n0 = blockIdx.y * 128;
    int b  = n0 / Tt;
    int t0 = n0 % Tt;

    const float* zb  = z  + (size_t)b * Dd * Tt + t0;  // A[nn][d] = zb[d*Tt + nn]
    const float* cbb = cb + (size_t)k0 * Dd;

    int tx = threadIdx.x & 15;   // k direction
    int ty = threadIdx.x >> 4;   // n direction

    float acc[8][8];
#pragma unroll
    for (int i = 0; i < 8; i++)
#pragma unroll
        for (int j = 0; j < 8; j++) acc[i][j] = 0.f;

    for (int d0 = 0; d0 < Dd; d0 += 16) {
        // load A tile: 16 d-rows x 128 n-cols (coalesced along t)
#pragma unroll
        for (int i = 0; i < 2; i++) {
            int s  = threadIdx.x + i * 256;       // 0..511 float4 slots
            int dd = s >> 5;
            int cq = (s & 31) << 2;
            float4 v = *(const float4*)(zb + (size_t)(d0 + dd) * Tt + cq);
            *(float4*)&As[dd][cq] = v;
        }
        // load B tile: 128 k-rows x 16 d-cols (coalesced along d)
#pragma unroll
        for (int i = 0; i < 2; i++) {
            int s  = threadIdx.x + i * 256;
            int kk = s >> 2;
            int dq = (s & 3) << 2;
            float4 v = *(const float4*)(cbb + (size_t)kk * Dd + d0 + dq);
            Bs[dq + 0][kk] = v.x;
            Bs[dq + 1][kk] = v.y;
            Bs[dq + 2][kk] = v.z;
            Bs[dq + 3][kk] = v.w;
        }
        __syncthreads();

#pragma unroll
        for (int dd = 0; dd < 16; dd++) {
            float a[8], bv[8];
            *(float4*)(a + 0)  = *(float4*)&As[dd][ty * 8 + 0];
            *(float4*)(a + 4)  = *(float4*)&As[dd][ty * 8 + 4];
            *(float4*)(bv + 0) = *(float4*)&Bs[dd][tx * 8 + 0];
            *(float4*)(bv + 4) = *(float4*)&Bs[dd][tx * 8 + 4];
#pragma unroll
            for (int i = 0; i < 8; i++)
#pragma unroll
                for (int j = 0; j < 8; j++) acc[i][j] += a[i] * bv[j];
        }
        __syncthreads();
    }

#pragma unroll
    for (int i = 0; i < 8; i++) {
        float* dst = g_dots + (size_t)(n0 + ty * 8 + i) * Kk + k0 + tx * 8;
        *(float4*)(dst + 0) = *(float4*)&acc[i][0];
        *(float4*)(dst + 4) = *(float4*)&acc[i][4];
    }
}

// ---------------------------------------------------------------------------
// argmin with reference rounding: d = fl(fl(S - 2*dot) + C2), first-index ties
// one warp per row n
// ---------------------------------------------------------------------------
__global__ void k_argmin() {
    int w = threadIdx.x >> 5, lane = threadIdx.x & 31;
    int n = blockIdx.x * 8 + w;
    float S = g_S[n];
    const float* row = g_dots + (size_t)n * Kk;

    float best = 3.4e38f;
    int   bk   = Kk;
    for (int k = lane; k < Kk; k += 32) {
        float m  = __fmul_rn(2.0f, row[k]);        // exact (power of 2)
        float v1 = __fadd_rn(S, -m);               // fl(S - 2*dot)
        float v  = __fadd_rn(v1, g_C2[k]);         // fl(... + C)
        if (v < best) { best = v; bk = k; }        // ascending k -> first index
    }
#pragma unroll
    for (int off = 16; off; off >>= 1) {
        float vo = __shfl_down_sync(0xFFFFFFFFu, best, off);
        int   ko = __shfl_down_sync(0xFFFFFFFFu, bk, off);
        if (vo < best || (vo == best && ko < bk)) { best = vo; bk = ko; }
    }
    if (lane == 0) g_idx[n] = bk;
}

// ---------------------------------------------------------------------------
// init onehot outputs with conv bias
// ---------------------------------------------------------------------------
__global__ void k_init(float* __restrict__ out, const float* __restrict__ cbias) {
    float bias = __ldg(cbias);
    int i = blockIdx.x * 256 + threadIdx.x;   // 0..16383
    out[OH1_OFF + i] = bias;
    out[OH2_OFF + i] = bias;
}

// ---------------------------------------------------------------------------
// scatter: z_q_x = fl(z + fl(q - z)), z_q_x_bar = q, plus conv partial sums
// block = (32 t) x (64 d) tile; codebook rows staged in SMEM
// ---------------------------------------------------------------------------
__global__ void __launch_bounds__(256) k_scatter(const float* __restrict__ z,
                                                 const float* __restrict__ cb,
                                                 const float* __restrict__ cw,
                                                 float* __restrict__ out) {
    __shared__ int   sidx[32];
    __shared__ float scb[32][65];       // stride 65 -> conflict-free by lane
    __shared__ float r1[8][33], r2[8][33];

    int b  = blockIdx.z;
    int d0 = blockIdx.y * 64;
    int t0 = blockIdx.x * 32;
    int w = threadIdx.x >> 5, lane = threadIdx.x & 31;

    if (threadIdx.x < 32) sidx[threadIdx.x] = g_idx[b * Tt + t0 + threadIdx.x];
    __syncthreads();

    // stage codebook rows: 32 rows x 64 floats
#pragma unroll
    for (int i = 0; i < 2; i++) {
        int s   = threadIdx.x + i * 256;     // 0..511 float4 slots
        int row = s >> 4;
        int q4  = (s & 15) << 2;
        float4 v = *(const float4*)(cb + (size_t)sidx[row] * Dd + d0 + q4);
        scb[row][q4 + 0] = v.x;
        scb[row][q4 + 1] = v.y;
        scb[row][q4 + 2] = v.z;
        scb[row][q4 + 3] = v.w;
    }
    __syncthreads();

    const float* zp = z   + (size_t)b * Dd * Tt + (size_t)d0 * Tt + t0 + lane;
    float*       o1 = out + (size_t)b * Dd * Tt + (size_t)d0 * Tt + t0 + lane;
    float*       o3 = o1 + BAR_OFF;

    float acc1 = 0.f, acc2 = 0.f;
#pragma unroll
    for (int j = 0; j < 8; j++) {
        int dl = w * 8 + j;
        float q  = scb[lane][dl];
        float zv = zp[(size_t)dl * Tt];
        float dqz = __fadd_rn(q, -zv);         // fl(q - z)
        float zq  = __fadd_rn(zv, dqz);        // fl(z + (q - z))
        o1[(size_t)dl * Tt] = zq;
        o3[(size_t)dl * Tt] = q;
        float wv = __ldg(cw + d0 + dl);
        acc1 += zq * wv;
        acc2 += q * wv;
    }
    r1[w][lane] = acc1;
    r2[w][lane] = acc2;
    __syncthreads();
    if (w == 0) {
        float s1 = 0.f, s2 = 0.f;
#pragma unroll
        for (int i = 0; i < 8; i++) { s1 += r1[i][lane]; s2 += r2[i][lane]; }
        atomicAdd(out + OH1_OFF + b * Tt + t0 + lane, s1);
        atomicAdd(out + OH2_OFF + b * Tt + t0 + lane, s2);
    }
}

// ---------------------------------------------------------------------------
extern "C" void kernel_launch(void* const* d_in, const int* in_sizes, int n_in,
                              void* d_out, int out_size) {
    const float* z      = (const float*)d_in[0];   // (B, D, T) = 33554432
    const float* cb     = (const float*)d_in[1];   // (K, D)    = 1048576
    const float* conv_w = (const float*)d_in[2];   // (D,)      = 2048
    const float* conv_b = (const float*)d_in[3];   // (1,)
    float* out = (float*)d_out;

    k_c2<<<Kk, 256>>>(cb);
    k_S<<<Nn / 256, 256>>>(z);
    k_gemm<<<dim3(Kk / 128, Nn / 128), 256>>>(z, cb);
    k_argmin<<<Nn / 8, 256>>>();
    k_init<<<Nn / 256, 256>>>(out, conv_b);
    k_scatter<<<dim3(Tt / 32, Dd / 64, Bb), 256>>>(z, cb, conv_w, out);
}

// round 4
// speedup vs baseline: 2.8947x; 2.8947x over previous
#include <cuda_runtime.h>
#include <cuda_bf16.h>
#include <cstdint>

#define Bb 32
#define Dd 2048
#define Tt 512
#define Kk 512
#define Nn (Bb*Tt)            // 16384
#define BDT (Bb*Dd*Tt)        // 33554432
#define OH1_OFF BDT
#define BAR_OFF (BDT + Nn)
#define OH2_OFF (2*BDT + Nn)
#define MAXC 32
#define MARGIN 1e-3f

// ---------------- scratch (device globals; allocation-free) ----------------
__device__ __nv_bfloat16 g_a0[(size_t)Nn * Dd];   // z bf16, n-major
__device__ float         g_at[(size_t)Nn * Dd];   // z fp32, n-major (exact)
__device__ __nv_bfloat16 g_b0[(size_t)Kk * Dd];   // codebook bf16
__device__ float g_dots[(size_t)Nn * Kk];         // approx scores
__device__ float g_S[Nn];
__device__ float g_C2[Kk];
__device__ int   g_cand[(size_t)Nn * MAXC];
__device__ int   g_ccount[Nn];
__device__ unsigned long long g_best[Nn];

__device__ __forceinline__ uint32_t smem_u32(const void* p) {
    uint32_t a;
    asm("{ .reg .u64 t; cvta.to.shared.u64 t, %1; cvt.u32.u64 %0, t; }" : "=r"(a) : "l"(p));
    return a;
}
__device__ __forceinline__ uint32_t sw_off(int r, int cbyte) {
    return (uint32_t)(r * 128 + (cbyte ^ ((r & 7) << 4)));
}

#define LDSM4(f, addr) \
    asm volatile("ldmatrix.sync.aligned.m8n8.x4.shared.b16 {%0,%1,%2,%3}, [%4];" \
        : "=r"((f)[0]), "=r"((f)[1]), "=r"((f)[2]), "=r"((f)[3]) : "r"(addr))

#define MMA16816(d, a, br0, br1) \
    asm volatile("mma.sync.aligned.m16n8k16.row.col.f32.bf16.bf16.f32 " \
        "{%0,%1,%2,%3}, {%4,%5,%6,%7}, {%8,%9}, {%0,%1,%2,%3};" \
        : "+f"((d)[0]), "+f"((d)[1]), "+f"((d)[2]), "+f"((d)[3]) \
        : "r"((a)[0]), "r"((a)[1]), "r"((a)[2]), "r"((a)[3]), "r"(br0), "r"(br1))

// ---------------------------------------------------------------------------
// codebook: C2 (R1-exact arithmetic) + bf16 copy
// ---------------------------------------------------------------------------
__global__ void k_prep_cb(const float* __restrict__ cb) {
    int k = blockIdx.x;
    const float4* row = (const float4*)(cb + (size_t)k * Dd);
    float s = 0.f;
    for (int i = threadIdx.x; i < Dd / 4; i += 256) {
        float4 v = row[i];
        s += v.x * v.x + v.y * v.y + v.z * v.z + v.w * v.w;
        __nv_bfloat16 h[4];
        h[0] = __float2bfloat16(v.x); h[1] = __float2bfloat16(v.y);
        h[2] = __float2bfloat16(v.z); h[3] = __float2bfloat16(v.w);
        *(uint2*)&g_b0[(size_t)k * Dd + 4 * i] = *(uint2*)h;
    }
    __shared__ float sm[256];
    sm[threadIdx.x] = s;
    __syncthreads();
    for (int o = 128; o; o >>= 1) {
        if (threadIdx.x < o) sm[threadIdx.x] += sm[threadIdx.x + o];
        __syncthreads();
    }
    if (threadIdx.x == 0) g_C2[k] = sm[0];
}

// ---------------------------------------------------------------------------
// z (B,D,T) -> n-major bf16 (for MMA) + n-major fp32 (exact, for refine)
// ---------------------------------------------------------------------------
__global__ void __launch_bounds__(256) k_prep_z(const float* __restrict__ z) {
    __shared__ float s[64][65];
    int t0 = blockIdx.x * 64;
    int d0 = blockIdx.y * 64;
    int b  = blockIdx.z;
    const float* zp = z + (size_t)b * Dd * Tt;

#pragma unroll
    for (int i = 0; i < 16; i++) {
        int e = i * 256 + threadIdx.x;
        int dr = e >> 6, tc = e & 63;
        s[dr][tc] = zp[(size_t)(d0 + dr) * Tt + t0 + tc];
    }
    __syncthreads();

#pragma unroll
    for (int i = 0; i < 4; i++) {
        int e = i * 256 + threadIdx.x;          // 0..1023
        int tr = e >> 4, dc = (e & 15) << 2;
        int n = b * Tt + t0 + tr;
        __nv_bfloat16 h0[4];
        float f[4];
#pragma unroll
        for (int j = 0; j < 4; j++) {
            f[j] = s[dc + j][tr];
            h0[j] = __float2bfloat16(f[j]);
        }
        *(uint2*)&g_a0[(size_t)n * Dd + d0 + dc] = *(uint2*)h0;
        *(float4*)&g_at[(size_t)n * Dd + d0 + dc] = *(float4*)f;
    }
}

// ---------------------------------------------------------------------------
// S[n] = sum_d z[b,d,t]^2  (R1-exact)
// ---------------------------------------------------------------------------
__global__ void k_S(const float* __restrict__ z) {
    int n = blockIdx.x * 256 + threadIdx.x;
    int b = n / Tt, t = n % Tt;
    const float* p = z + (size_t)b * Dd * Tt + t;
    float a0 = 0.f, a1 = 0.f, a2 = 0.f, a3 = 0.f;
#pragma unroll 4
    for (int d = 0; d < Dd; d += 4) {
        float v0 = p[(size_t)(d + 0) * Tt];
        float v1 = p[(size_t)(d + 1) * Tt];
        float v2 = p[(size_t)(d + 2) * Tt];
        float v3 = p[(size_t)(d + 3) * Tt];
        a0 += v0 * v0; a1 += v1 * v1; a2 += v2 * v2; a3 += v3 * v3;
    }
    g_S[n] = (a0 + a1) + (a2 + a3);
}

// ---------------------------------------------------------------------------
// single-pass bf16 mma.sync GEMM: dots[n,k] ~= sum_d a[n,d]*b[k,d]
// CTA 128x128, BK=64, 3-stage cp.async pipeline
// ---------------------------------------------------------------------------
#define TILE_BYTES 16384
#define STAGE_BYTES (2*TILE_BYTES)
#define SM_SZ (3*STAGE_BYTES)      // 98304

__global__ void __launch_bounds__(256) k_gemm_mma() {
    extern __shared__ char sm[];
    const int tid  = threadIdx.x;
    const int lane = tid & 31, wid = tid >> 5;
    const int mw = wid & 1, nw = wid >> 1;
    const int n0 = blockIdx.y * 128;
    const int k0 = blockIdx.x * 128;

    const __nv_bfloat16* srcs[2];
    srcs[0] = g_a0 + (size_t)n0 * Dd;
    srcs[1] = g_b0 + (size_t)k0 * Dd;

    const uint32_t smbase = smem_u32(sm);

    auto stage_load = [&](int kt, int slot) {
        const int d0 = kt * 64;
        const uint32_t sbase = smbase + slot * STAGE_BYTES;
#pragma unroll
        for (int i = 0; i < 8; i++) {
            int q = i * 256 + tid;              // 0..2047 16B chunks
            int tile = q >> 10;
            int qq = q & 1023;
            int r = qq >> 3, c16 = (qq & 7) << 4;
            uint32_t dst = sbase + tile * TILE_BYTES + sw_off(r, c16);
            const void* src = (const char*)(srcs[tile] + (size_t)r * Dd + d0) + c16;
            asm volatile("cp.async.cg.shared.global [%0], [%1], 16;" :: "r"(dst), "l"(src));
        }
        asm volatile("cp.async.commit_group;" ::: "memory");
    };

    float acc[4][4][4];
#pragma unroll
    for (int a = 0; a < 4; a++)
#pragma unroll
        for (int b = 0; b < 4; b++)
#pragma unroll
            for (int c = 0; c < 4; c++) acc[a][b][c] = 0.f;

    stage_load(0, 0);
    stage_load(1, 1);

    for (int kt = 0; kt < 32; kt++) {
        asm volatile("cp.async.wait_group 1;" ::: "memory");
        __syncthreads();
        if (kt + 2 < 32) stage_load(kt + 2, (kt + 2) % 3);

        const uint32_t sb  = smbase + (kt % 3) * STAGE_BYTES;
        const uint32_t a0b = sb;
        const uint32_t b0b = sb + TILE_BYTES;

#pragma unroll
        for (int kk = 0; kk < 4; kk++) {
            const int cba = kk * 32 + ((lane >> 4) & 1) * 16;
            const int cbb = kk * 32 + ((lane >> 3) & 1) * 16;
            uint32_t a0f[4][4];
#pragma unroll
            for (int mi = 0; mi < 4; mi++) {
                int r = mw * 64 + mi * 16 + (lane & 15);
                LDSM4(a0f[mi], a0b + sw_off(r, cba));
            }
            uint32_t b0f[2][4];
#pragma unroll
            for (int nj = 0; nj < 2; nj++) {
                int r = nw * 32 + nj * 16 + (lane & 7) + ((lane >> 4) & 1) * 8;
                LDSM4(b0f[nj], b0b + sw_off(r, cbb));
            }
#pragma unroll
            for (int mi = 0; mi < 4; mi++)
#pragma unroll
                for (int ni = 0; ni < 4; ni++) {
                    const uint32_t* p0 = &b0f[ni >> 1][(ni & 1) * 2];
                    MMA16816(acc[mi][ni], a0f[mi], p0[0], p0[1]);
                }
        }
    }

#pragma unroll
    for (int mi = 0; mi < 4; mi++) {
        int rbase = n0 + mw * 64 + mi * 16 + (lane >> 2);
#pragma unroll
        for (int ni = 0; ni < 4; ni++) {
            int c = k0 + nw * 32 + ni * 8 + (lane & 3) * 2;
            *(float2*)&g_dots[(size_t)rbase * Kk + c]       = make_float2(acc[mi][ni][0], acc[mi][ni][1]);
            *(float2*)&g_dots[(size_t)(rbase + 8) * Kk + c] = make_float2(acc[mi][ni][2], acc[mi][ni][3]);
        }
    }
}

// ---------------------------------------------------------------------------
// approx argmin + candidate shortlist (all k with v <= best + MARGIN)
// ---------------------------------------------------------------------------
__global__ void k_argmin() {
    int w = threadIdx.x >> 5, lane = threadIdx.x & 31;
    int n = blockIdx.x * 8 + w;
    float S = g_S[n];
    const float* row = g_dots + (size_t)n * Kk;

    float v[16];
    float best = 3.4e38f;
    int   bk   = Kk;
#pragma unroll
    for (int i = 0; i < 16; i++) {
        int k = i * 32 + lane;
        float m  = __fmul_rn(2.0f, row[k]);
        float v1 = __fadd_rn(S, -m);
        v[i] = __fadd_rn(v1, g_C2[k]);
        if (v[i] < best) { best = v[i]; bk = k; }
    }
#pragma unroll
    for (int off = 16; off; off >>= 1) {
        float vo = __shfl_down_sync(0xFFFFFFFFu, best, off);
        int   ko = __shfl_down_sync(0xFFFFFFFFu, bk, off);
        if (vo < best || (vo == best && ko < bk)) { best = vo; bk = ko; }
    }
    best = __shfl_sync(0xFFFFFFFFu, best, 0);
    bk   = __shfl_sync(0xFFFFFFFFu, bk, 0);

    float thr = best + MARGIN;
    int base = 0;
#pragma unroll
    for (int i = 0; i < 16; i++) {
        bool f = (v[i] <= thr);
        unsigned m = __ballot_sync(0xFFFFFFFFu, f);
        if (f) {
            int slot = base + __popc(m & ((1u << lane) - 1));
            if (slot < MAXC) g_cand[(size_t)n * MAXC + slot] = i * 32 + lane;
        }
        base += __popc(m);
    }
    if (lane == 0) {
        int cnt = base;
        if (cnt > MAXC) {                      // overflow insurance: keep approx-best
            g_cand[(size_t)n * MAXC + MAXC - 1] = bk;
            cnt = MAXC;
        }
        g_ccount[n] = cnt;
    }
}

// ---------------------------------------------------------------------------
// init outputs' onehot bias + g_best
// ---------------------------------------------------------------------------
__global__ void k_init(float* __restrict__ out, const float* __restrict__ cbias) {
    float bias = __ldg(cbias);
    int i = blockIdx.x * 256 + threadIdx.x;
    out[OH1_OFF + i] = bias;
    out[OH2_OFF + i] = bias;
    g_best[i] = 0xFFFFFFFFFFFFFFFFull;
}

// ---------------------------------------------------------------------------
// exact fp32 re-evaluation of candidates; warp per row
// ---------------------------------------------------------------------------
__global__ void __launch_bounds__(256) k_refine(const float* __restrict__ cb) {
    int n = blockIdx.x * 8 + (threadIdx.x >> 5);
    int lane = threadIdx.x & 31;
    int cnt = g_ccount[n];
    float S = g_S[n];
    const float* arow = g_at + (size_t)n * Dd;

    for (int c = 0; c < cnt; c++) {
        int k = g_cand[(size_t)n * MAXC + c];
        const float* brow = cb + (size_t)k * Dd;
        float acc = 0.f;
#pragma unroll
        for (int j = 0; j < 16; j++) {
            int d = j * 128 + lane * 4;
            float4 a = *(const float4*)(arow + d);
            float4 b = *(const float4*)(brow + d);
            acc = fmaf(a.x, b.x, acc);
            acc = fmaf(a.y, b.y, acc);
            acc = fmaf(a.z, b.z, acc);
            acc = fmaf(a.w, b.w, acc);
        }
#pragma unroll
        for (int off = 16; off; off >>= 1)
            acc += __shfl_down_sync(0xFFFFFFFFu, acc, off);
        if (lane == 0) {
            float v1 = __fadd_rn(S, -__fmul_rn(2.0f, acc));
            float vv = __fadd_rn(v1, g_C2[k]);
            unsigned long long key =
                ((unsigned long long)__float_as_uint(vv) << 32) | (unsigned)k;
            atomicMin(&g_best[n], key);
        }
    }
}

// ---------------------------------------------------------------------------
__global__ void __launch_bounds__(256) k_scatter(const float* __restrict__ z,
                                                 const float* __restrict__ cb,
                                                 const float* __restrict__ cw,
                                                 float* __restrict__ out) {
    __shared__ int   sidx[32];
    __shared__ float scb[32][65];
    __shared__ float r1[8][33], r2[8][33];

    int b  = blockIdx.z;
    int d0 = blockIdx.y * 64;
    int t0 = blockIdx.x * 32;
    int w = threadIdx.x >> 5, lane = threadIdx.x & 31;

    if (threadIdx.x < 32)
        sidx[threadIdx.x] = (int)(g_best[b * Tt + t0 + threadIdx.x] & 0xFFFFFFFFull);
    __syncthreads();

#pragma unroll
    for (int i = 0; i < 2; i++) {
        int s   = threadIdx.x + i * 256;
        int row = s >> 4;
        int q4  = (s & 15) << 2;
        float4 v = *(const float4*)(cb + (size_t)sidx[row] * Dd + d0 + q4);
        scb[row][q4 + 0] = v.x;
        scb[row][q4 + 1] = v.y;
        scb[row][q4 + 2] = v.z;
        scb[row][q4 + 3] = v.w;
    }
    __syncthreads();

    const float* zp = z   + (size_t)b * Dd * Tt + (size_t)d0 * Tt + t0 + lane;
    float*       o1 = out + (size_t)b * Dd * Tt + (size_t)d0 * Tt + t0 + lane;
    float*       o3 = o1 + BAR_OFF;

    float acc1 = 0.f, acc2 = 0.f;
#pragma unroll
    for (int j = 0; j < 8; j++) {
        int dl = w * 8 + j;
        float q  = scb[lane][dl];
        float zv = zp[(size_t)dl * Tt];
        float dqz = __fadd_rn(q, -zv);
        float zq  = __fadd_rn(zv, dqz);
        o1[(size_t)dl * Tt] = zq;
        o3[(size_t)dl * Tt] = q;
        float wv = __ldg(cw + d0 + dl);
        acc1 += zq * wv;
        acc2 += q * wv;
    }
    r1[w][lane] = acc1;
    r2[w][lane] = acc2;
    __syncthreads();
    if (w == 0) {
        float s1 = 0.f, s2 = 0.f;
#pragma unroll
        for (int i = 0; i < 8; i++) { s1 += r1[i][lane]; s2 += r2[i][lane]; }
        atomicAdd(out + OH1_OFF + b * Tt + t0 + lane, s1);
        atomicAdd(out + OH2_OFF + b * Tt + t0 + lane, s2);
    }
}

// ---------------------------------------------------------------------------
extern "C" void kernel_launch(void* const* d_in, const int* in_sizes, int n_in,
                              void* d_out, int out_size) {
    const float* z      = (const float*)d_in[0];
    const float* cb     = (const float*)d_in[1];
    const float* conv_w = (const float*)d_in[2];
    const float* conv_b = (const float*)d_in[3];
    float* out = (float*)d_out;

    cudaFuncSetAttribute(k_gemm_mma, cudaFuncAttributeMaxDynamicSharedMemorySize, SM_SZ);

    k_prep_cb<<<Kk, 256>>>(cb);
    k_prep_z<<<dim3(Tt / 64, Dd / 64, Bb), 256>>>(z);
    k_S<<<Nn / 256, 256>>>(z);
    k_gemm_mma<<<dim3(Kk / 128, Nn / 128), 256, SM_SZ>>>();
    k_argmin<<<Nn / 8, 256>>>();
    k_init<<<Nn / 256, 256>>>(out, conv_b);
    k_refine<<<Nn / 8, 256>>>(cb);
    k_scatter<<<dim3(Tt / 32, Dd / 64, Bb), 256>>>(z, cb, conv_w, out);
}